// round 11
// baseline (speedup 1.0000x reference)
#include <cuda_runtime.h>
#include <math.h>

// MNN forward, two kernels.
//  build_k: ONE block builds q/e/g (dx=0.005, 1813 pts), f32 shuffle trapezoid
//    scans for D1, h, D2, normalizes at x=0, emits every 2nd node as
//    {D1, D2, G, h} (dx_tab = 0.01, 907 entries, 14.5 KB).
//  mnn_main: smem table; per element the TWO queries (ub, lb) run PACKED in
//    f32x2 (fma.rn.f32x2): magic-number nearest-node round + 2nd-order Taylor
//      D1' = G, D2' = h, G' = 2xG+1, h' = 2xh + G^2, G'' = 2G + 2xG'.
// Queries provably in [-6.71, 2.24] -> node j in [9, 904], no clamps.

#define NB    1813
#define DXB   0.005f
#define I0B   1360
#define NT    907
#define BTPB  1024
#define BCH   2
#define TPB   256
#define NBLK  912           // 6 per SM on 152 SMs

// f32x2 constants as 64-bit immediates (lo | hi), both lanes equal
#define C_RDXT2   0x42C8000042C80000ULL   // 100.0f
#define C_I0MAG2  0x4B4002A84B4002A8ULL   // 680 + 1.5*2^23 = 12583592.0f
#define C_NMAG2   0xCB400000CB400000ULL   // -12582912.0f
#define C_DXT2    0x3C23D70A3C23D70AULL   // 0.01f
#define C_X02     0xC0D9999AC0D9999AULL   // -6.8f
#define C_NEG12   0xBF800000BF800000ULL   // -1.0f
#define C_HALF2   0x3F0000003F000000ULL   // 0.5f
#define C_ONE2    0x3F8000003F800000ULL   // 1.0f
#define MAGIC_I   0x4B400000

typedef unsigned long long f2_t;

__device__ __forceinline__ f2_t pk2(float lo, float hi) {
    f2_t r; asm("mov.b64 %0, {%1, %2};" : "=l"(r) : "f"(lo), "f"(hi)); return r;
}
__device__ __forceinline__ void upk2(f2_t v, float& lo, float& hi) {
    asm("mov.b64 {%0, %1}, %2;" : "=f"(lo), "=f"(hi) : "l"(v));
}
__device__ __forceinline__ void upk2i(f2_t v, int& lo, int& hi) {
    asm("mov.b64 {%0, %1}, %2;" : "=r"(lo), "=r"(hi) : "l"(v));
}
__device__ __forceinline__ f2_t fma2(f2_t a, f2_t b, f2_t c) {
    f2_t r; asm("fma.rn.f32x2 %0, %1, %2, %3;" : "=l"(r) : "l"(a), "l"(b), "l"(c)); return r;
}
__device__ __forceinline__ f2_t add2(f2_t a, f2_t b) {
    f2_t r; asm("add.rn.f32x2 %0, %1, %2;" : "=l"(r) : "l"(a), "l"(b)); return r;
}
__device__ __forceinline__ f2_t mul2(f2_t a, f2_t b) {
    f2_t r; asm("mul.rn.f32x2 %0, %1, %2;" : "=l"(r) : "l"(a), "l"(b)); return r;
}

__device__ float4 gT[NT];   // {D1, D2, G, h}

// ---------------- build kernel (single block, shuffle scans) ----------------
__device__ __forceinline__ float b_excl_scan(float v, float* wpart) {
    const int lane = threadIdx.x & 31;
    const int w    = threadIdx.x >> 5;
    float x = v;
    #pragma unroll
    for (int off = 1; off < 32; off <<= 1) {
        float y = __shfl_up_sync(0xffffffffu, x, off);
        if (lane >= off) x += y;
    }
    if (lane == 31) wpart[w] = x;
    __syncthreads();
    if (w == 0) {
        float p = wpart[lane];
        #pragma unroll
        for (int off = 1; off < 32; off <<= 1) {
            float y = __shfl_up_sync(0xffffffffu, p, off);
            if (lane >= off) p += y;
        }
        wpart[lane] = p;
    }
    __syncthreads();
    float base = (w > 0) ? wpart[w - 1] : 0.0f;
    return base + x - v;
}

__global__ void __launch_bounds__(BTPB) build_k() {
    __shared__ float4 B[NB];       // .x=q/D1  .y=h  .z=e/D2  .w=g
    __shared__ float  wpart[32];

    const int t  = threadIdx.x;
    const int lo = t * BCH;
    const int hi = min(lo + BCH, NB);
    const int lo1 = max(lo, 1);

    for (int i = lo; i < hi; ++i) {
        float x  = fmaf((float)i, DXB, -6.8f);
        float e  = expf(x * x);
        float er = erfcf(-x);
        B[i] = make_float4(0.78539816339744831f * e * er * er, 0.0f, e,
                           0.88622692545275801f * e * er);
    }
    __syncthreads();

    float sum = 0.0f;
    for (int i = lo1; i < hi; ++i) sum += 0.5f * (B[i].x + B[i - 1].x) * DXB;
    float run = b_excl_scan(sum, wpart);
    __syncthreads();
    for (int i = lo; i < hi; ++i) {
        if (i >= 1) run += 0.5f * (B[i].x + B[i - 1].x) * DXB;
        B[i].y = B[i].z * run;
    }
    __syncthreads();

    sum = 0.0f;
    for (int i = lo1; i < hi; ++i) sum += 0.5f * (B[i].y + B[i - 1].y) * DXB;
    run = b_excl_scan(sum, wpart);
    __syncthreads();
    for (int i = lo; i < hi; ++i) {
        if (i >= 1) run += 0.5f * (B[i].y + B[i - 1].y) * DXB;
        B[i].z = run;
    }
    __syncthreads();

    sum = 0.0f;
    for (int i = lo1; i < hi; ++i) sum += 0.5f * (B[i].w + B[i - 1].w) * DXB;
    run = b_excl_scan(sum, wpart);
    __syncthreads();
    for (int i = lo; i < hi; ++i) {
        if (i >= 1) run += 0.5f * (B[i].w + B[i - 1].w) * DXB;
        B[i].x = run;
    }
    __syncthreads();

    float c1 = B[I0B].x;
    float c2 = B[I0B].z;
    __syncthreads();
    for (int j = t; j < NT; j += BTPB) {
        float4 v = B[2 * j];
        gT[j] = make_float4(v.x - c1, v.z - c2, v.w, v.y);   // {D1, D2, G, h}
    }
}

// ---------------- main kernel ------------------------------------------------
__device__ __forceinline__ void mnn_one(float u, float s,
                                        const float4* __restrict__ T,
                                        float& ua_o, float& sa_o, float& chi_o) {
    bool idx1 = (s > 0.0f) && ((1.0f - u) < 2.2360679774997896f * s);
    bool idx2 = (s <= 0.0f) && (u > 1.0f);

    float ssafe = idx1 ? s : 1.0f;
    float rden  = __fdividef(4.4721359549995794f, ssafe);   // 1/(sqrt(L)*s)
    float ub = (1.0f - u) * rden;
    float lb = -u * rden;

    // ---- packed dual query: lane0 = ub, lane1 = lb ----
    f2_t P  = pk2(ub, lb);
    f2_t FI = fma2(P, C_RDXT2, C_I0MAG2);      // magic round to nearest node
    int j1, j2;
    upk2i(FI, j1, j2);
    j1 -= MAGIC_I;  j2 -= MAGIC_I;
    f2_t RJ = add2(FI, C_NMAG2);               // node index as float
    f2_t XJ = fma2(RJ, C_DXT2, C_X02);         // node x
    f2_t Tt = fma2(XJ, C_NEG12, P);            // t = x - xj, |t| <= dx/2

    float4 a = T[j1];
    float4 b = T[j2];
    f2_t Gz = pk2(a.z, b.z);
    f2_t Hw = pk2(a.w, b.w);
    f2_t D1 = pk2(a.x, b.x);
    f2_t D2 = pk2(a.y, b.y);

    f2_t TX  = add2(XJ, XJ);                   // 2x
    f2_t GP  = fma2(TX, Gz, C_ONE2);           // G'  = 2xG + 1
    f2_t GG  = mul2(Gz, Gz);
    f2_t HP  = fma2(TX, Hw, GG);               // h'  = 2xh + G^2
    f2_t G2  = add2(Gz, Gz);
    f2_t GPP = fma2(TX, GP, G2);               // G'' = 2xG' + 2G
    f2_t HT  = mul2(Tt, C_HALF2);              // t/2
    f2_t D1v = fma2(Tt, fma2(HT, GP,  Gz), D1);
    f2_t D2v = fma2(Tt, fma2(HT, HP,  Hw), D2);
    f2_t Gv  = fma2(Tt, fma2(HT, GPP, GP), Gz);

    float d1u, d1l, d2u, d2l, gu, gl;
    upk2(D1v, d1u, d1l);
    upk2(D2v, d2u, d2l);
    upk2(Gv,  gu,  gl);
    float dd1 = d1u - d1l;
    float dd2 = d2u - d2l;
    float dg  = gu  - gl;

    float ua1 = 40.0f * dd1;                                // 2/L

    float usafe = idx2 ? u : 2.0f;
    float num = usafe - 1.0f;                               // exact (Sterbenz)
    float lg  = __logf(__fdividef(num, usafe));             // log(1 - 1/u)
    float isi2 = fmaf(-20.0f, lg, 5.0f);
    float ua2 = __fdividef(1.0f, isi2);
    float ua = idx1 ? ua1 : (idx2 ? ua2 : 0.0f);

    // s_a nonzero only in region 1
    float ua1sq = ua1 * ua1;
    float prod = (3200.0f * dd2) * ua1sq * ua1;
    bool  pos  = idx1 && (prod > 0.0f);
    float rs   = rsqrtf(prod);
    float sa   = pos ? prod * rs : 0.0f;
    float rsa  = pos ? rs : 1.0f;

    float chi1 = ua1sq * rsa * (dg * 178.88543819998318f);  // 2/L^1.5
    float term = idx2 ? (2.0f * u - 1.0f) : 1.0f;
    float chi2 = 6.324555320336759f * rsqrtf(isi2 * term);  // sqrt(2/L)
    float chi = idx1 ? chi1 : (idx2 ? chi2 : 0.0f);

    ua_o = ua; sa_o = sa; chi_o = chi;
}

__global__ void __launch_bounds__(TPB, 6)
mnn_main(const float* __restrict__ u, const float* __restrict__ s,
         float* __restrict__ out, int n) {
    __shared__ float4 T[NT];          // 14.5 KB

    for (int i = threadIdx.x; i < NT; i += TPB) T[i] = gT[i];
    __syncthreads();

    int gtid = blockIdx.x * blockDim.x + threadIdx.x;
    int stride = gridDim.x * blockDim.x;

    if ((n & 3) == 0) {
        int n4 = n >> 2;
        const float4* u4 = (const float4*)u;
        const float4* s4 = (const float4*)s;
        float4* o0 = (float4*)out;
        float4* o1 = (float4*)(out + n);
        float4* o2 = (float4*)(out + 2 * n);
        for (int idx = gtid; idx < n4; idx += stride) {
            float4 uu = u4[idx], ss = s4[idx];
            float4 a, b, c;
            mnn_one(uu.x, ss.x, T, a.x, b.x, c.x);
            mnn_one(uu.y, ss.y, T, a.y, b.y, c.y);
            mnn_one(uu.z, ss.z, T, a.z, b.z, c.z);
            mnn_one(uu.w, ss.w, T, a.w, b.w, c.w);
            o0[idx] = a; o1[idx] = b; o2[idx] = c;
        }
    } else {
        for (int idx = gtid; idx < n; idx += stride) {
            float a, b, c;
            mnn_one(u[idx], s[idx], T, a, b, c);
            out[idx] = a; out[n + idx] = b; out[2 * n + idx] = c;
        }
    }
}

extern "C" void kernel_launch(void* const* d_in, const int* in_sizes, int n_in,
                              void* d_out, int out_size) {
    const float* u = (const float*)d_in[0];
    const float* s = (const float*)d_in[1];
    float* out = (float*)d_out;
    int n = in_sizes[0];

    build_k<<<1, BTPB>>>();
    mnn_main<<<NBLK, TPB>>>(u, s, out, n);
}

// round 15
// speedup vs baseline: 1.7459x; 1.7459x over previous
#include <cuda_runtime.h>
#include <math.h>

// MNN forward, two kernels.
//  build_k: ONE block builds q/e/g (dx=0.005, 1813 pts), f32 shuffle trapezoid
//    scans for D1, h, D2, normalizes at x=0, emits ALL nodes as {D1, D2, G, h}.
//  mnn_main: 29 KB smem table; per query ONE LDS.128 + 1st-order Taylor with
//    exact derivatives:  D1' = G, D2' = h, G' = 2xG+1.
//  Nearest-node rounding via magic-number trick (no F2I/I2F).
// Queries provably in [-6.71, 2.24] -> interior nodes, no clamps.

#define NB    1813          // grid: x = -6.8 + i*0.005
#define DXB   0.005f
#define I0B   1360          // x = 0
#define NT    1813
#define I0T   1360.0f
#define RDXT  200.0f        // 1/dx
#define DXT   0.005f
#define MAGIC 12582912.0f   // 1.5 * 2^23
#define MAGIC_I 0x4B400000
#define BTPB  1024
#define BCH   2
#define TPB   256
#define NBLK  912           // 6 per SM on 152 SMs

__device__ float4 gT[NT];   // {D1, D2, G, h}

// ---------------- build kernel (single block, shuffle scans) ----------------
__device__ __forceinline__ float b_excl_scan(float v, float* wpart) {
    const int lane = threadIdx.x & 31;
    const int w    = threadIdx.x >> 5;
    float x = v;
    #pragma unroll
    for (int off = 1; off < 32; off <<= 1) {
        float y = __shfl_up_sync(0xffffffffu, x, off);
        if (lane >= off) x += y;
    }
    if (lane == 31) wpart[w] = x;
    __syncthreads();
    if (w == 0) {
        float p = wpart[lane];
        #pragma unroll
        for (int off = 1; off < 32; off <<= 1) {
            float y = __shfl_up_sync(0xffffffffu, p, off);
            if (lane >= off) p += y;
        }
        wpart[lane] = p;
    }
    __syncthreads();
    float base = (w > 0) ? wpart[w - 1] : 0.0f;
    return base + x - v;
}

__global__ void __launch_bounds__(BTPB) build_k() {
    __shared__ float4 B[NB];       // .x=q/D1  .y=h  .z=e/D2  .w=g
    __shared__ float  wpart[32];

    const int t  = threadIdx.x;
    const int lo = t * BCH;
    const int hi = min(lo + BCH, NB);
    const int lo1 = max(lo, 1);

    // pointwise: .x = q, .z = e, .w = g
    for (int i = lo; i < hi; ++i) {
        float x  = fmaf((float)i, DXB, -6.8f);
        float e  = expf(x * x);
        float er = erfcf(-x);
        B[i] = make_float4(0.78539816339744831f * e * er * er, 0.0f, e,
                           0.88622692545275801f * e * er);
    }
    __syncthreads();

    // scan q -> cq ; h = e*cq -> .y
    float sum = 0.0f;
    for (int i = lo1; i < hi; ++i) sum += 0.5f * (B[i].x + B[i - 1].x) * DXB;
    float run = b_excl_scan(sum, wpart);
    __syncthreads();
    for (int i = lo; i < hi; ++i) {
        if (i >= 1) run += 0.5f * (B[i].x + B[i - 1].x) * DXB;
        B[i].y = B[i].z * run;
    }
    __syncthreads();

    // scan h -> D2 -> .z
    sum = 0.0f;
    for (int i = lo1; i < hi; ++i) sum += 0.5f * (B[i].y + B[i - 1].y) * DXB;
    run = b_excl_scan(sum, wpart);
    __syncthreads();
    for (int i = lo; i < hi; ++i) {
        if (i >= 1) run += 0.5f * (B[i].y + B[i - 1].y) * DXB;
        B[i].z = run;
    }
    __syncthreads();

    // scan g (.w) -> D1 -> .x
    sum = 0.0f;
    for (int i = lo1; i < hi; ++i) sum += 0.5f * (B[i].w + B[i - 1].w) * DXB;
    run = b_excl_scan(sum, wpart);
    __syncthreads();
    for (int i = lo; i < hi; ++i) {
        if (i >= 1) run += 0.5f * (B[i].w + B[i - 1].w) * DXB;
        B[i].x = run;
    }
    __syncthreads();

    // normalize at x = 0, emit all nodes: {D1, D2, G, h}
    float c1 = B[I0B].x;
    float c2 = B[I0B].z;
    __syncthreads();
    for (int j = t; j < NT; j += BTPB) {
        float4 v = B[j];
        gT[j] = make_float4(v.x - c1, v.z - c2, v.w, v.y);
    }
}

// ---------------- main kernel ------------------------------------------------
__device__ __forceinline__ void mnn_one(float u, float s,
                                        const float4* __restrict__ T,
                                        float& ua_o, float& sa_o, float& chi_o) {
    bool idx1 = (s > 0.0f) && ((1.0f - u) < 2.2360679774997896f * s);
    bool idx2 = (s <= 0.0f) && (u > 1.0f);

    float ssafe = idx1 ? s : 1.0f;
    float rden  = __fdividef(4.4721359549995794f, ssafe);   // 1/(sqrt(L)*s)
    float ub = (1.0f - u) * rden;
    float lb = -u * rden;

    // ---- query at ub: magic-number nearest node + 1st-order Taylor ----
    float fi1 = fmaf(ub, RDXT, I0T + MAGIC);
    float rj1 = fi1 - MAGIC;
    int   j1  = __float_as_int(fi1) - MAGIC_I;
    float xj1 = fmaf(rj1, DXT, -6.8f);
    float t1  = ub - xj1;                                   // |t| <= dx/2
    float4 a = T[j1];
    float Gp1 = fmaf(xj1 + xj1, a.z, 1.0f);                 // G' = 2xG+1
    float d1u = fmaf(t1, a.z, a.x);                         // D1 + t G
    float d2u = fmaf(t1, a.w, a.y);                         // D2 + t h
    float gu  = fmaf(t1, Gp1, a.z);                         // G  + t G'

    // ---- query at lb ----
    float fi2 = fmaf(lb, RDXT, I0T + MAGIC);
    float rj2 = fi2 - MAGIC;
    int   j2  = __float_as_int(fi2) - MAGIC_I;
    float xj2 = fmaf(rj2, DXT, -6.8f);
    float t2  = lb - xj2;
    float4 b = T[j2];
    float Gp2 = fmaf(xj2 + xj2, b.z, 1.0f);
    float d1l = fmaf(t2, b.z, b.x);
    float d2l = fmaf(t2, b.w, b.y);
    float gl  = fmaf(t2, Gp2, b.z);

    float ua1 = 40.0f * (d1u - d1l);                        // 2/L

    float usafe = idx2 ? u : 2.0f;
    float num = usafe - 1.0f;                               // exact (Sterbenz)
    float lg  = __logf(__fdividef(num, usafe));             // log(1 - 1/u)
    float isi2 = fmaf(-20.0f, lg, 5.0f);
    float ua2 = __fdividef(1.0f, isi2);
    float ua = idx1 ? ua1 : (idx2 ? ua2 : 0.0f);

    // s_a nonzero only in region 1
    float ua1sq = ua1 * ua1;
    float prod = (3200.0f * (d2u - d2l)) * ua1sq * ua1;
    bool  pos  = idx1 && (prod > 0.0f);
    float rs   = rsqrtf(prod);
    float sa   = pos ? prod * rs : 0.0f;
    float rsa  = pos ? rs : 1.0f;

    float chi1 = ua1sq * rsa * ((gu - gl) * 178.88543819998318f);  // 2/L^1.5
    float term = idx2 ? (2.0f * u - 1.0f) : 1.0f;
    float chi2 = 6.324555320336759f * rsqrtf(isi2 * term);         // sqrt(2/L)
    float chi = idx1 ? chi1 : (idx2 ? chi2 : 0.0f);

    ua_o = ua; sa_o = sa; chi_o = chi;
}

__global__ void __launch_bounds__(TPB, 6)
mnn_main(const float* __restrict__ u, const float* __restrict__ s,
         float* __restrict__ out, int n) {
    __shared__ float4 T[NT];          // 29 KB

    for (int i = threadIdx.x; i < NT; i += TPB) T[i] = gT[i];
    __syncthreads();

    int gtid = blockIdx.x * blockDim.x + threadIdx.x;
    int stride = gridDim.x * blockDim.x;

    if ((n & 3) == 0) {
        int n4 = n >> 2;
        const float4* u4 = (const float4*)u;
        const float4* s4 = (const float4*)s;
        float4* o0 = (float4*)out;
        float4* o1 = (float4*)(out + n);
        float4* o2 = (float4*)(out + 2 * n);
        for (int idx = gtid; idx < n4; idx += stride) {
            float4 uu = u4[idx], ss = s4[idx];
            float4 a, b, c;
            mnn_one(uu.x, ss.x, T, a.x, b.x, c.x);
            mnn_one(uu.y, ss.y, T, a.y, b.y, c.y);
            mnn_one(uu.z, ss.z, T, a.z, b.z, c.z);
            mnn_one(uu.w, ss.w, T, a.w, b.w, c.w);
            o0[idx] = a; o1[idx] = b; o2[idx] = c;
        }
    } else {
        for (int idx = gtid; idx < n; idx += stride) {
            float a, b, c;
            mnn_one(u[idx], s[idx], T, a, b, c);
            out[idx] = a; out[n + idx] = b; out[2 * n + idx] = c;
        }
    }
}

extern "C" void kernel_launch(void* const* d_in, const int* in_sizes, int n_in,
                              void* d_out, int out_size) {
    const float* u = (const float*)d_in[0];
    const float* s = (const float*)d_in[1];
    float* out = (float*)d_out;
    int n = in_sizes[0];

    build_k<<<1, BTPB>>>();
    mnn_main<<<NBLK, TPB>>>(u, s, out, n);
}

// round 16
// speedup vs baseline: 1.7523x; 1.0036x over previous
#include <cuda_runtime.h>
#include <math.h>

// MNN forward, two kernels.
//  build_k: ONE block builds q/e/g (dx=0.005, 1813 pts), f32 shuffle trapezoid
//    scans for D1, h, D2, normalizes at x=0, emits all nodes PRE-SCALED:
//       {40*D1, 40*G, 3200*D2, 3200*h}
//  mnn_main: 29 KB smem table; per query ONE LDS.128 + 1st-order Taylor with
//    exact derivatives (D1'=G, D2'=h, G'=2xG+1; scaled: Ghat' = 2x*Ghat + 40).
//  Magic-number nearest-node round (no F2I/I2F). Input loads software-
//  pipelined one grid-stride iteration ahead (double buffer).
// Queries provably in [-6.71, 2.24] -> interior nodes, no clamps.

#define NB    1813          // grid: x = -6.8 + i*0.005
#define DXB   0.005f
#define I0B   1360          // x = 0
#define NT    1813
#define I0T   1360.0f
#define RDXT  200.0f        // 1/dx
#define DXT   0.005f
#define MAGIC 12582912.0f   // 1.5 * 2^23
#define MAGIC_I 0x4B400000
#define BTPB  1024
#define BCH   2
#define TPB   256
#define NBLK  760           // 5 per SM on 152 SMs

__device__ float4 gT[NT];   // {40*D1, 40*G, 3200*D2, 3200*h}

// ---------------- build kernel (single block, shuffle scans) ----------------
__device__ __forceinline__ float b_excl_scan(float v, float* wpart) {
    const int lane = threadIdx.x & 31;
    const int w    = threadIdx.x >> 5;
    float x = v;
    #pragma unroll
    for (int off = 1; off < 32; off <<= 1) {
        float y = __shfl_up_sync(0xffffffffu, x, off);
        if (lane >= off) x += y;
    }
    if (lane == 31) wpart[w] = x;
    __syncthreads();
    if (w == 0) {
        float p = wpart[lane];
        #pragma unroll
        for (int off = 1; off < 32; off <<= 1) {
            float y = __shfl_up_sync(0xffffffffu, p, off);
            if (lane >= off) p += y;
        }
        wpart[lane] = p;
    }
    __syncthreads();
    float base = (w > 0) ? wpart[w - 1] : 0.0f;
    return base + x - v;
}

__global__ void __launch_bounds__(BTPB) build_k() {
    __shared__ float4 B[NB];       // .x=q/D1  .y=h  .z=e/D2  .w=g
    __shared__ float  wpart[32];

    const int t  = threadIdx.x;
    const int lo = t * BCH;
    const int hi = min(lo + BCH, NB);
    const int lo1 = max(lo, 1);

    // pointwise: .x = q, .z = e, .w = g
    for (int i = lo; i < hi; ++i) {
        float x  = fmaf((float)i, DXB, -6.8f);
        float e  = expf(x * x);
        float er = erfcf(-x);
        B[i] = make_float4(0.78539816339744831f * e * er * er, 0.0f, e,
                           0.88622692545275801f * e * er);
    }
    __syncthreads();

    // scan q -> cq ; h = e*cq -> .y
    float sum = 0.0f;
    for (int i = lo1; i < hi; ++i) sum += 0.5f * (B[i].x + B[i - 1].x) * DXB;
    float run = b_excl_scan(sum, wpart);
    __syncthreads();
    for (int i = lo; i < hi; ++i) {
        if (i >= 1) run += 0.5f * (B[i].x + B[i - 1].x) * DXB;
        B[i].y = B[i].z * run;
    }
    __syncthreads();

    // scan h -> D2 -> .z
    sum = 0.0f;
    for (int i = lo1; i < hi; ++i) sum += 0.5f * (B[i].y + B[i - 1].y) * DXB;
    run = b_excl_scan(sum, wpart);
    __syncthreads();
    for (int i = lo; i < hi; ++i) {
        if (i >= 1) run += 0.5f * (B[i].y + B[i - 1].y) * DXB;
        B[i].z = run;
    }
    __syncthreads();

    // scan g (.w) -> D1 -> .x
    sum = 0.0f;
    for (int i = lo1; i < hi; ++i) sum += 0.5f * (B[i].w + B[i - 1].w) * DXB;
    run = b_excl_scan(sum, wpart);
    __syncthreads();
    for (int i = lo; i < hi; ++i) {
        if (i >= 1) run += 0.5f * (B[i].w + B[i - 1].w) * DXB;
        B[i].x = run;
    }
    __syncthreads();

    // normalize at x = 0, emit all nodes pre-scaled
    float c1 = B[I0B].x;
    float c2 = B[I0B].z;
    __syncthreads();
    for (int j = t; j < NT; j += BTPB) {
        float4 v = B[j];
        gT[j] = make_float4(40.0f * (v.x - c1), 40.0f * v.w,
                            3200.0f * (v.z - c2), 3200.0f * v.y);
    }
}

// ---------------- main kernel ------------------------------------------------
__device__ __forceinline__ void mnn_one(float u, float s,
                                        const float4* __restrict__ T,
                                        float& ua_o, float& sa_o, float& chi_o) {
    bool idx1 = (s > 0.0f) && ((1.0f - u) < 2.2360679774997896f * s);
    bool idx2 = (s <= 0.0f) && (u > 1.0f);

    float ssafe = idx1 ? s : 1.0f;
    float rden  = __fdividef(4.4721359549995794f, ssafe);   // 1/(sqrt(L)*s)
    float ub = (1.0f - u) * rden;
    float lb = -u * rden;

    // ---- query at ub: magic-number nearest node + 1st-order Taylor ----
    float fi1 = fmaf(ub, RDXT, I0T + MAGIC);
    float rj1 = fi1 - MAGIC;
    int   j1  = __float_as_int(fi1) - MAGIC_I;
    float xj1 = fmaf(rj1, DXT, -6.8f);
    float t1  = ub - xj1;                                   // |t| <= dx/2
    float4 a = T[j1];
    float Gp1 = fmaf(xj1 + xj1, a.y, 40.0f);                // Ghat' = 2x Ghat + 40
    float d1u = fmaf(t1, a.y, a.x);                         // 40*(D1 + t G)
    float d2u = fmaf(t1, a.w, a.z);                         // 3200*(D2 + t h)
    float gu  = fmaf(t1, Gp1, a.y);                         // 40*(G + t G')

    // ---- query at lb ----
    float fi2 = fmaf(lb, RDXT, I0T + MAGIC);
    float rj2 = fi2 - MAGIC;
    int   j2  = __float_as_int(fi2) - MAGIC_I;
    float xj2 = fmaf(rj2, DXT, -6.8f);
    float t2  = lb - xj2;
    float4 b = T[j2];
    float Gp2 = fmaf(xj2 + xj2, b.y, 40.0f);
    float d1l = fmaf(t2, b.y, b.x);
    float d2l = fmaf(t2, b.w, b.z);
    float gl  = fmaf(t2, Gp2, b.y);

    float ua1 = d1u - d1l;                                  // already *40 = 2/L

    float usafe = idx2 ? u : 2.0f;
    float num = usafe - 1.0f;                               // exact (Sterbenz)
    float lg  = __logf(__fdividef(num, usafe));             // log(1 - 1/u)
    float isi2 = fmaf(-20.0f, lg, 5.0f);
    float ua2 = __fdividef(1.0f, isi2);
    float ua = idx1 ? ua1 : (idx2 ? ua2 : 0.0f);

    // s_a nonzero only in region 1
    float ua1sq = ua1 * ua1;
    float prod = (d2u - d2l) * ua1sq * ua1;                 // 3200*dd2 folded
    bool  pos  = idx1 && (prod > 0.0f);
    float rs   = rsqrtf(prod);
    float sa   = pos ? prod * rs : 0.0f;
    float rsa  = pos ? rs : 1.0f;

    float chi1 = ua1sq * rsa * ((gu - gl) * 4.4721359549995794f);  // 178.885/40
    float term = idx2 ? (2.0f * u - 1.0f) : 1.0f;
    float chi2 = 6.324555320336759f * rsqrtf(isi2 * term);         // sqrt(2/L)
    float chi = idx1 ? chi1 : (idx2 ? chi2 : 0.0f);

    ua_o = ua; sa_o = sa; chi_o = chi;
}

__global__ void __launch_bounds__(TPB, 5)
mnn_main(const float* __restrict__ u, const float* __restrict__ s,
         float* __restrict__ out, int n) {
    __shared__ float4 T[NT];          // 29 KB

    for (int i = threadIdx.x; i < NT; i += TPB) T[i] = gT[i];
    __syncthreads();

    int gtid = blockIdx.x * blockDim.x + threadIdx.x;
    int stride = gridDim.x * blockDim.x;

    if ((n & 3) == 0) {
        int n4 = n >> 2;
        const float4* u4 = (const float4*)u;
        const float4* s4 = (const float4*)s;
        float4* o0 = (float4*)out;
        float4* o1 = (float4*)(out + n);
        float4* o2 = (float4*)(out + 2 * n);

        int idx = gtid;
        if (idx < n4) {
            float4 uu = u4[idx], ss = s4[idx];
            for (;;) {
                // prefetch next iteration's inputs before computing
                int nidx = idx + stride;
                bool more = nidx < n4;
                float4 un, sn;
                if (more) { un = u4[nidx]; sn = s4[nidx]; }

                float4 a, b, c;
                mnn_one(uu.x, ss.x, T, a.x, b.x, c.x);
                mnn_one(uu.y, ss.y, T, a.y, b.y, c.y);
                mnn_one(uu.z, ss.z, T, a.z, b.z, c.z);
                mnn_one(uu.w, ss.w, T, a.w, b.w, c.w);
                o0[idx] = a; o1[idx] = b; o2[idx] = c;

                if (!more) break;
                idx = nidx; uu = un; ss = sn;
            }
        }
    } else {
        for (int idx = gtid; idx < n; idx += stride) {
            float a, b, c;
            mnn_one(u[idx], s[idx], T, a, b, c);
            out[idx] = a; out[n + idx] = b; out[2 * n + idx] = c;
        }
    }
}

extern "C" void kernel_launch(void* const* d_in, const int* in_sizes, int n_in,
                              void* d_out, int out_size) {
    const float* u = (const float*)d_in[0];
    const float* s = (const float*)d_in[1];
    float* out = (float*)d_out;
    int n = in_sizes[0];

    build_k<<<1, BTPB>>>();
    mnn_main<<<NBLK, TPB>>>(u, s, out, n);
}

// round 17
// speedup vs baseline: 1.9215x; 1.0965x over previous
#include <cuda_runtime.h>
#include <math.h>

// MNN forward, two kernels.
//  build_k: ONE block, 907-node grid (dx=0.01), trapezoid scans with
//    Euler-Maclaurin endpoint correction (-dx^2/12 * f') -> O(dx^4) node
//    accuracy using exact derivatives:
//      g' = 2xg+1,  q' = 2xq + 2g/e,  h' = 2xh + e*q.
//    Emits all nodes PRE-SCALED: {40*D1, 40*G, 3200*D2, 3200*h}.
//  mnn_main: 14.5 KB smem table; per query ONE LDS.128 + 1st-order Taylor
//    with exact derivatives (D1'=G, D2'=h; scaled Ghat' = 2x*Ghat + 40).
//  Magic-number nearest-node round (no F2I/I2F).
// Queries provably in [-6.71, 2.24] -> interior nodes, no clamps.

#define NT    907           // grid: x = -6.8 + i*0.01
#define DXB   0.01f
#define EMC   8.3333333e-6f // dx^2 / 12
#define I0B   680           // x = 0
#define I0T   680.0f
#define RDXT  100.0f        // 1/dx
#define DXT   0.01f
#define MAGIC 12582912.0f   // 1.5 * 2^23
#define MAGIC_I 0x4B400000
#define BTPB  1024
#define TPB   256
#define NBLK  912           // 6 per SM on 152 SMs

__device__ float4 gT[NT];   // {40*D1, 40*G, 3200*D2, 3200*h}

// inclusive block scan over BTPB floats (shuffle + one smem hop)
__device__ __forceinline__ float b_incl_scan(float v, float* wpart) {
    const int lane = threadIdx.x & 31;
    const int w    = threadIdx.x >> 5;
    float x = v;
    #pragma unroll
    for (int off = 1; off < 32; off <<= 1) {
        float y = __shfl_up_sync(0xffffffffu, x, off);
        if (lane >= off) x += y;
    }
    if (lane == 31) wpart[w] = x;
    __syncthreads();
    if (w == 0) {
        float p = wpart[lane];
        #pragma unroll
        for (int off = 1; off < 32; off <<= 1) {
            float y = __shfl_up_sync(0xffffffffu, p, off);
            if (lane >= off) p += y;
        }
        wpart[lane] = p;
    }
    __syncthreads();
    float r = x + ((w > 0) ? wpart[w - 1] : 0.0f);
    __syncthreads();
    return r;
}

__global__ void __launch_bounds__(BTPB) build_k() {
    __shared__ float4 B[NT];       // fields evolve: {q/D1, h, e/D2, g}
    __shared__ float  wpart[32];

    const int t = threadIdx.x;
    const bool own = (t < NT);

    // pointwise: .x = q, .z = e, .w = g
    float q = 0.0f, e = 1.0f, g = 0.0f, x = 0.0f;
    if (own) {
        x  = fmaf((float)t, DXB, -6.8f);
        e  = expf(x * x);
        float er = erfcf(-x);
        g  = 0.88622692545275801f * e * er;
        q  = 0.78539816339744831f * e * er * er;
        B[t] = make_float4(q, 0.0f, e, g);
    }
    __syncthreads();

    // ---- scan q -> cq ; EM-correct ; h = e * cqc -> .y ----
    float inc = (own && t >= 1) ? 0.5f * (B[t].x + B[t - 1].x) * DXB : 0.0f;
    float cq = b_incl_scan(inc, wpart);
    float h = 0.0f;
    if (own) {
        // q' = 2xq + 2 g / e
        float qp = fmaf(2.0f * x, q, 2.0f * __fdividef(g, e));
        float cqc = fmaf(-EMC, qp, cq);
        h = e * cqc;
        B[t].y = h;
    }
    __syncthreads();

    // ---- scan h -> D2 ; EM-correct ; -> .z ----
    inc = (own && t >= 1) ? 0.5f * (B[t].y + B[t - 1].y) * DXB : 0.0f;
    float d2 = b_incl_scan(inc, wpart);
    if (own) {
        // h' = 2xh + e*q
        float hp = fmaf(2.0f * x, h, e * q);
        B[t].z = fmaf(-EMC, hp, d2);
    }
    __syncthreads();

    // ---- scan g -> D1 ; EM-correct ; -> .x ----
    inc = (own && t >= 1) ? 0.5f * (B[t].w + B[t - 1].w) * DXB : 0.0f;
    float d1 = b_incl_scan(inc, wpart);
    if (own) {
        // g' = 2xg + 1
        float gp = fmaf(2.0f * x, g, 1.0f);
        B[t].x = fmaf(-EMC, gp, d1);
    }
    __syncthreads();

    // ---- normalize at x = 0 (node I0B), emit pre-scaled ----
    float c1 = B[I0B].x;
    float c2 = B[I0B].z;
    __syncthreads();
    if (own) {
        float4 v = B[t];
        gT[t] = make_float4(40.0f * (v.x - c1), 40.0f * v.w,
                            3200.0f * (v.z - c2), 3200.0f * v.y);
    }
}

// ---------------- main kernel ------------------------------------------------
__device__ __forceinline__ void mnn_one(float u, float s,
                                        const float4* __restrict__ T,
                                        float& ua_o, float& sa_o, float& chi_o) {
    bool idx1 = (s > 0.0f) && ((1.0f - u) < 2.2360679774997896f * s);
    bool idx2 = (s <= 0.0f) && (u > 1.0f);

    float ssafe = idx1 ? s : 1.0f;
    float rden  = __fdividef(4.4721359549995794f, ssafe);   // 1/(sqrt(L)*s)
    float ub = (1.0f - u) * rden;
    float lb = -u * rden;

    // ---- query at ub: magic-number nearest node + 1st-order Taylor ----
    float fi1 = fmaf(ub, RDXT, I0T + MAGIC);
    float rj1 = fi1 - MAGIC;
    int   j1  = __float_as_int(fi1) - MAGIC_I;
    float xj1 = fmaf(rj1, DXT, -6.8f);
    float t1  = ub - xj1;                                   // |t| <= dx/2
    float4 a = T[j1];
    float Gp1 = fmaf(xj1 + xj1, a.y, 40.0f);                // Ghat' = 2x Ghat + 40
    float d1u = fmaf(t1, a.y, a.x);                         // 40*(D1 + t G)
    float d2u = fmaf(t1, a.w, a.z);                         // 3200*(D2 + t h)
    float gu  = fmaf(t1, Gp1, a.y);                         // 40*(G + t G')

    // ---- query at lb ----
    float fi2 = fmaf(lb, RDXT, I0T + MAGIC);
    float rj2 = fi2 - MAGIC;
    int   j2  = __float_as_int(fi2) - MAGIC_I;
    float xj2 = fmaf(rj2, DXT, -6.8f);
    float t2  = lb - xj2;
    float4 b = T[j2];
    float Gp2 = fmaf(xj2 + xj2, b.y, 40.0f);
    float d1l = fmaf(t2, b.y, b.x);
    float d2l = fmaf(t2, b.w, b.z);
    float gl  = fmaf(t2, Gp2, b.y);

    float ua1 = d1u - d1l;                                  // already = 2/L * dD1

    float usafe = idx2 ? u : 2.0f;
    float num = usafe - 1.0f;                               // exact (Sterbenz)
    float lg  = __logf(__fdividef(num, usafe));             // log(1 - 1/u)
    float isi2 = fmaf(-20.0f, lg, 5.0f);
    float ua2 = __fdividef(1.0f, isi2);
    float ua = idx1 ? ua1 : (idx2 ? ua2 : 0.0f);

    // s_a nonzero only in region 1
    float ua1sq = ua1 * ua1;
    float prod = (d2u - d2l) * ua1sq * ua1;                 // 3200*dd2 folded
    bool  pos  = idx1 && (prod > 0.0f);
    float rs   = rsqrtf(prod);
    float sa   = pos ? prod * rs : 0.0f;
    float rsa  = pos ? rs : 1.0f;

    float chi1 = ua1sq * rsa * ((gu - gl) * 4.4721359549995794f);  // 178.885/40
    float term = idx2 ? (2.0f * u - 1.0f) : 1.0f;
    float chi2 = 6.324555320336759f * rsqrtf(isi2 * term);         // sqrt(2/L)
    float chi = idx1 ? chi1 : (idx2 ? chi2 : 0.0f);

    ua_o = ua; sa_o = sa; chi_o = chi;
}

__global__ void __launch_bounds__(TPB, 6)
mnn_main(const float* __restrict__ u, const float* __restrict__ s,
         float* __restrict__ out, int n) {
    __shared__ float4 T[NT];          // 14.5 KB

    for (int i = threadIdx.x; i < NT; i += TPB) T[i] = gT[i];
    __syncthreads();

    int gtid = blockIdx.x * blockDim.x + threadIdx.x;
    int stride = gridDim.x * blockDim.x;

    if ((n & 3) == 0) {
        int n4 = n >> 2;
        const float4* u4 = (const float4*)u;
        const float4* s4 = (const float4*)s;
        float4* o0 = (float4*)out;
        float4* o1 = (float4*)(out + n);
        float4* o2 = (float4*)(out + 2 * n);
        for (int idx = gtid; idx < n4; idx += stride) {
            float4 uu = u4[idx], ss = s4[idx];
            float4 a, b, c;
            mnn_one(uu.x, ss.x, T, a.x, b.x, c.x);
            mnn_one(uu.y, ss.y, T, a.y, b.y, c.y);
            mnn_one(uu.z, ss.z, T, a.z, b.z, c.z);
            mnn_one(uu.w, ss.w, T, a.w, b.w, c.w);
            o0[idx] = a; o1[idx] = b; o2[idx] = c;
        }
    } else {
        for (int idx = gtid; idx < n; idx += stride) {
            float a, b, c;
            mnn_one(u[idx], s[idx], T, a, b, c);
            out[idx] = a; out[n + idx] = b; out[2 * n + idx] = c;
        }
    }
}

extern "C" void kernel_launch(void* const* d_in, const int* in_sizes, int n_in,
                              void* d_out, int out_size) {
    const float* u = (const float*)d_in[0];
    const float* s = (const float*)d_in[1];
    float* out = (float*)d_out;
    int n = in_sizes[0];

    build_k<<<1, BTPB>>>();
    mnn_main<<<NBLK, TPB>>>(u, s, out, n);
}